// round 1
// baseline (speedup 1.0000x reference)
#include <cuda_runtime.h>

// SSIM3D: x,y are (2, 4, 128, 128, 128) fp32. 5x5x5 Gaussian depthwise conv
// (sigma=1.5) is exactly separable; output is the scalar mean of the SSIM map.
//
// Fully fused: one streaming kernel does (x+1)*0.5 transform, separable
// W->H conv of {x, y, x^2, y^2, x*y} per D-slice, a 5-deep register ring for
// the D-direction conv, the pointwise SSIM formula, and a hierarchical
// reduction into a __device__ double accumulator. No intermediates in HBM.

#define D_ 128
#define H_ 128
#define W_ 128
#define WT 32            // output tile width
#define HT 16            // output tile height
#define WS (WT + 4)      // 36: haloed tile width
#define HS (HT + 4)      // 20: haloed tile height
#define NTH 512          // threads per block = WT * HT
#define NVOX (2.0 * 4.0 * 128.0 * 128.0 * 128.0)

__device__ double g_sum;

__global__ void ssim3d_init_kernel() { g_sum = 0.0; }

__global__ void ssim3d_finalize_kernel(float* __restrict__ out) {
    out[0] = (float)(g_sum * (1.0 / NVOX));
}

__global__ __launch_bounds__(NTH) void ssim3d_main_kernel(
    const float* __restrict__ x, const float* __restrict__ y) {

    // Normalized 1D Gaussian weights (sigma=1.5). exp(-1/4.5), exp(-4/4.5).
    constexpr double G1 = 0.8007374029168081;   // e^{-2/9}
    constexpr double G0 = 0.4111122904071876;   // e^{-8/9}
    constexpr double S1 = 1.0 + 2.0 * (G0 + G1);
    const float Wk[5] = {(float)(G0 / S1), (float)(G1 / S1), (float)(1.0 / S1),
                         (float)(G1 / S1), (float)(G0 / S1)};

    __shared__ float sx[HS][WS];          // haloed raw x slice (transformed)
    __shared__ float sy[HS][WS];          // haloed raw y slice (transformed)
    __shared__ float si[5][HS][WT];       // W-convolved {m1,m2,xx,yy,xy}
    __shared__ float wsum[NTH / 32];

    const int tid = threadIdx.x;
    const int lw  = tid & 31;             // w within tile
    const int lh  = tid >> 5;             // h within tile
    const int wtile = (blockIdx.x & 3) * WT;
    const int htile = (blockIdx.x >> 2) * HT;
    const size_t base = (size_t)(blockIdx.z * 4 + blockIdx.y) * (D_ * H_ * W_);

    // Ring of 5 D-slices x 5 quantities, in registers (fully unrolled indices).
    float ring[5][5];
#pragma unroll
    for (int s = 0; s < 5; s++)
#pragma unroll
        for (int j = 0; j < 5; j++) ring[s][j] = 0.0f;

    float acc = 0.0f;

    for (int dd = 0; dd < D_ + 2; ++dd) {
        float nv[5];
        if (dd < D_) {
            // ---- load haloed slice dd into SMEM (zero pad OOB) ----
            const float* xp = x + base + (size_t)dd * (H_ * W_);
            const float* yp = y + base + (size_t)dd * (H_ * W_);
            for (int i = tid; i < HS * WS; i += NTH) {
                int r = i / WS;
                int c = i - r * WS;
                int gh = htile - 2 + r;
                int gw = wtile - 2 + c;
                float xv = 0.0f, yv = 0.0f;
                if ((unsigned)gh < (unsigned)H_ && (unsigned)gw < (unsigned)W_) {
                    int gi = gh * W_ + gw;
                    xv = (xp[gi] + 1.0f) * 0.5f;
                    yv = (yp[gi] + 1.0f) * 0.5f;
                }
                sx[r][c] = xv;
                sy[r][c] = yv;
            }
            __syncthreads();

            // ---- step 1: W-direction conv at HS x WT points ----
            for (int p = tid; p < HS * WT; p += NTH) {
                int r = p >> 5;
                int c = p & 31;
                float m1 = 0.f, m2 = 0.f, xx = 0.f, yy = 0.f, xy = 0.f;
#pragma unroll
                for (int k = 0; k < 5; k++) {
                    float xv = sx[r][c + k];
                    float yv = sy[r][c + k];
                    float wx = Wk[k] * xv;
                    float wy = Wk[k] * yv;
                    m1 += wx;
                    m2 += wy;
                    xx = fmaf(wx, xv, xx);
                    yy = fmaf(wy, yv, yy);
                    xy = fmaf(wx, yv, xy);
                }
                si[0][r][c] = m1;
                si[1][r][c] = m2;
                si[2][r][c] = xx;
                si[3][r][c] = yy;
                si[4][r][c] = xy;
            }
            __syncthreads();

            // ---- step 2: H-direction conv at own (lh, lw) ----
#pragma unroll
            for (int j = 0; j < 5; j++) {
                float v = 0.f;
#pragma unroll
                for (int k = 0; k < 5; k++)
                    v = fmaf(Wk[k], si[j][lh + k][lw], v);
                nv[j] = v;
            }
        } else {
#pragma unroll
            for (int j = 0; j < 5; j++) nv[j] = 0.0f;
        }

        // ---- shift ring, insert new slice ----
#pragma unroll
        for (int s = 0; s < 4; s++)
#pragma unroll
            for (int j = 0; j < 5; j++) ring[s][j] = ring[s + 1][j];
#pragma unroll
        for (int j = 0; j < 5; j++) ring[4][j] = nv[j];

        // ---- D-direction combine + SSIM for output slice dd-2 ----
        if (dd >= 2) {
            float M[5];
#pragma unroll
            for (int j = 0; j < 5; j++) {
                float v = 0.f;
#pragma unroll
                for (int s = 0; s < 5; s++)
                    v = fmaf(Wk[s], ring[s][j], v);
                M[j] = v;
            }
            float mu1 = M[0], mu2 = M[1];
            float mu1s = mu1 * mu1;
            float mu2s = mu2 * mu2;
            float mu12 = mu1 * mu2;
            float s1  = M[2] - mu1s;
            float s2  = M[3] - mu2s;
            float s12 = M[4] - mu12;
            const float C1 = 1e-4f;
            const float C2 = 9e-4f;
            float num = (2.0f * mu12 + C1) * (2.0f * s12 + C2);
            float den = (mu1s + mu2s + C1) * (s1 + s2 + C2);
            acc += num / den;
        }
    }

    // ---- reduction: warp shuffle -> SMEM -> one double atomicAdd ----
#pragma unroll
    for (int off = 16; off > 0; off >>= 1)
        acc += __shfl_xor_sync(0xFFFFFFFFu, acc, off);
    if ((tid & 31) == 0) wsum[tid >> 5] = acc;
    __syncthreads();
    if (tid == 0) {
        double s = 0.0;
#pragma unroll
        for (int i = 0; i < NTH / 32; i++) s += (double)wsum[i];
        atomicAdd(&g_sum, s);
    }
}

extern "C" void kernel_launch(void* const* d_in, const int* in_sizes, int n_in,
                              void* d_out, int out_size) {
    const float* x = (const float*)d_in[0];
    const float* y = (const float*)d_in[1];
    // d_in[2] is the Gaussian kernel; weights are compile-time constants here.
    float* out = (float*)d_out;

    ssim3d_init_kernel<<<1, 1>>>();
    dim3 grid(32, 4, 2);   // (h_tiles*w_tiles, C, N)
    ssim3d_main_kernel<<<grid, NTH>>>(x, y);
    ssim3d_finalize_kernel<<<1, 1>>>(out);
}

// round 2
// speedup vs baseline: 1.0335x; 1.0335x over previous
#include <cuda_runtime.h>

// SSIM3D, fully fused, separable 5-tap Gaussian (sigma=1.5), mean-reduced.
// R2: D-split x4 (grid 1024) + packed f32x2 arithmetic (x/y and quantity
// pairs ride one 64-bit lane: fma.rn.f32x2), packed 64-bit SMEM, fast div.

#define D_ 128
#define H_ 128
#define W_ 128
#define WT 32            // output tile width
#define HT 16            // output tile height
#define WS (WT + 4)      // 36
#define HS (HT + 4)      // 20
#define NTH 512
#define DCHUNK 32
#define NVOX (2.0 * 4.0 * 128.0 * 128.0 * 128.0)

typedef unsigned long long u64;

__device__ __forceinline__ u64 pk2(float lo, float hi) {
    u64 r; asm("mov.b64 %0,{%1,%2};" : "=l"(r) : "f"(lo), "f"(hi)); return r;
}
__device__ __forceinline__ void up2(u64 v, float& lo, float& hi) {
    asm("mov.b64 {%0,%1},%2;" : "=f"(lo), "=f"(hi) : "l"(v));
}
__device__ __forceinline__ u64 fma2_(u64 a, u64 b, u64 c) {
    u64 d; asm("fma.rn.f32x2 %0,%1,%2,%3;" : "=l"(d) : "l"(a), "l"(b), "l"(c)); return d;
}
__device__ __forceinline__ u64 mul2_(u64 a, u64 b) {
    u64 d; asm("mul.rn.f32x2 %0,%1,%2;" : "=l"(d) : "l"(a), "l"(b)); return d;
}
__device__ __forceinline__ u64 add2_(u64 a, u64 b) {
    u64 d; asm("add.rn.f32x2 %0,%1,%2;" : "=l"(d) : "l"(a), "l"(b)); return d;
}

__device__ double g_sum;

__global__ void ssim3d_init_kernel() { g_sum = 0.0; }

__global__ void ssim3d_finalize_kernel(float* __restrict__ out) {
    out[0] = (float)(g_sum * (1.0 / NVOX));
}

__global__ __launch_bounds__(NTH) void ssim3d_main_kernel(
    const float* __restrict__ x, const float* __restrict__ y) {

    // Normalized 1D Gaussian weights (sigma = 1.5).
    constexpr double G1 = 0.8007374029168081;   // e^{-2/9}
    constexpr double G0 = 0.4111122904071876;   // e^{-8/9}
    constexpr double S1 = 1.0 + 2.0 * (G0 + G1);
    const float wk[5] = {(float)(G0 / S1), (float)(G1 / S1), (float)(1.0 / S1),
                         (float)(G1 / S1), (float)(G0 / S1)};
    u64 wk2[5];
#pragma unroll
    for (int k = 0; k < 5; k++) wk2[k] = pk2(wk[k], wk[k]);
    const u64 HALF2 = pk2(0.5f, 0.5f);

    __shared__ u64   sraw[HS][WS];     // packed (x, y), transformed
    __shared__ u64   s_m12[HS][WT];    // packed (m1, m2) after W-conv
    __shared__ u64   s_xxyy[HS][WT];   // packed (xx, yy) after W-conv
    __shared__ float s_xy[HS][WT];     // xy after W-conv
    __shared__ float wsum[NTH / 32];

    const int tid = threadIdx.x;
    const int lw  = tid & 31;
    const int lh  = tid >> 5;
    const int wtile = (blockIdx.x & 3) * WT;
    const int htile = (blockIdx.x >> 2) * HT;
    const int d0    = blockIdx.y * DCHUNK;
    const size_t base = (size_t)blockIdx.z * (D_ * H_ * W_);

    // D-direction ring: 5 slices of (m12 pair, xxyy pair, xy scalar).
    u64 rm[5], rx[5]; float rz[5];
#pragma unroll
    for (int s = 0; s < 5; s++) { rm[s] = 0ull; rx[s] = 0ull; rz[s] = 0.0f; }

    float acc = 0.0f;

    for (int it = 0; it < DCHUNK + 4; ++it) {
        const int dd = d0 - 2 + it;
        u64 nm = 0ull, nx = 0ull; float nz = 0.0f;

        if ((unsigned)dd < (unsigned)D_) {
            // ---- load haloed slice dd, transform, pack (x,y) ----
            const float* xp = x + base + (size_t)dd * (H_ * W_);
            const float* yp = y + base + (size_t)dd * (H_ * W_);
            for (int i = tid; i < HS * WS; i += NTH) {
                int r = i / WS;
                int c = i - r * WS;
                int gh = htile - 2 + r;
                int gw = wtile - 2 + c;
                u64 v = 0ull;
                if ((unsigned)gh < (unsigned)H_ && (unsigned)gw < (unsigned)W_) {
                    int gi = gh * W_ + gw;
                    v = fma2_(pk2(xp[gi], yp[gi]), HALF2, HALF2);
                }
                sraw[r][c] = v;
            }
            __syncthreads();

            // ---- W-direction conv at HS x WT = 640 points ----
#pragma unroll
            for (int ph = 0; ph < 2; ph++) {
                int p = tid + ph * NTH;
                if (p < HS * WT) {
                    int r = p >> 5;
                    int c = p & 31;
                    u64 m12 = 0ull, xxyy = 0ull; float xyv = 0.0f;
#pragma unroll
                    for (int k = 0; k < 5; k++) {
                        u64 v  = sraw[r][c + k];
                        u64 wv = mul2_(wk2[k], v);
                        m12  = add2_(m12, wv);
                        xxyy = fma2_(wv, v, xxyy);
                        float wxv, wyv, xv, yv;
                        up2(wv, wxv, wyv);
                        up2(v, xv, yv);
                        xyv = fmaf(wxv, yv, xyv);
                    }
                    s_m12[r][c]  = m12;
                    s_xxyy[r][c] = xxyy;
                    s_xy[r][c]   = xyv;
                }
            }
            __syncthreads();

            // ---- H-direction conv at own (lh, lw) ----
#pragma unroll
            for (int k = 0; k < 5; k++) {
                nm = fma2_(wk2[k], s_m12[lh + k][lw], nm);
                nx = fma2_(wk2[k], s_xxyy[lh + k][lw], nx);
                nz = fmaf(wk[k], s_xy[lh + k][lw], nz);
            }
        }

        // ---- shift ring, insert new slice ----
#pragma unroll
        for (int s = 0; s < 4; s++) {
            rm[s] = rm[s + 1]; rx[s] = rx[s + 1]; rz[s] = rz[s + 1];
        }
        rm[4] = nm; rx[4] = nx; rz[4] = nz;

        // ---- D-direction combine + SSIM for output slice dd-2 ----
        if (it >= 4) {
            u64 M12 = 0ull, XXYY = 0ull; float XY = 0.0f;
#pragma unroll
            for (int s = 0; s < 5; s++) {
                M12  = fma2_(wk2[s], rm[s], M12);
                XXYY = fma2_(wk2[s], rx[s], XXYY);
                XY   = fmaf(wk[s], rz[s], XY);
            }
            float mu1, mu2, Sxx, Syy;
            up2(M12, mu1, mu2);
            up2(XXYY, Sxx, Syy);
            float mu1s = mu1 * mu1;
            float mu2s = mu2 * mu2;
            float mu12 = mu1 * mu2;
            float s1  = Sxx - mu1s;
            float s2  = Syy - mu2s;
            float s12 = XY  - mu12;
            const float C1 = 1e-4f;
            const float C2 = 9e-4f;
            float num = (2.0f * mu12 + C1) * (2.0f * s12 + C2);
            float den = (mu1s + mu2s + C1) * (s1 + s2 + C2);
            acc += __fdividef(num, den);
        }
    }

    // ---- reduction: warp shuffle -> SMEM -> one double atomicAdd ----
#pragma unroll
    for (int off = 16; off > 0; off >>= 1)
        acc += __shfl_xor_sync(0xFFFFFFFFu, acc, off);
    if ((tid & 31) == 0) wsum[tid >> 5] = acc;
    __syncthreads();
    if (tid == 0) {
        double s = 0.0;
#pragma unroll
        for (int i = 0; i < NTH / 32; i++) s += (double)wsum[i];
        atomicAdd(&g_sum, s);
    }
}

extern "C" void kernel_launch(void* const* d_in, const int* in_sizes, int n_in,
                              void* d_out, int out_size) {
    const float* x = (const float*)d_in[0];
    const float* y = (const float*)d_in[1];
    float* out = (float*)d_out;

    ssim3d_init_kernel<<<1, 1>>>();
    dim3 grid(32, 4, 8);   // (h_tiles * w_tiles, d_chunks, N*C)
    ssim3d_main_kernel<<<grid, NTH>>>(x, y);
    ssim3d_finalize_kernel<<<1, 1>>>(out);
}